// round 1
// baseline (speedup 1.0000x reference)
#include <cuda_runtime.h>

#define T_DIM 1024
#define B_DIM 128
#define D_DIM 256
#define H_DIM 256

// Scratch (allocation-free rule: __device__ globals).
// g_xdot padded by B_DIM extra float4 so the recurrence prefetch at t=T-1 stays in bounds.
__device__ __align__(16) float g_xdot[(T_DIM * B_DIM + B_DIM) * 4];
__device__ __align__(16) float g_h[T_DIM * B_DIM];
__device__ __align__(16) float g_c[B_DIM];

// ---- fast math helpers -----------------------------------------------------
__device__ __forceinline__ float sin_ap(float x) {
    float r; asm("sin.approx.f32 %0, %1;" : "=f"(r) : "f"(x)); return r;
}
__device__ __forceinline__ float ex2_ap(float x) {
    float r; asm("ex2.approx.f32 %0, %1;" : "=f"(r) : "f"(x)); return r;
}
__device__ __forceinline__ float rcp_ap(float x) {
    float r; asm("rcp.approx.f32 %0, %1;" : "=f"(r) : "f"(x)); return r;
}
// sigmoid(x) = 1 / (1 + 2^(-x*log2 e))   (accurate: ex2/rcp rel err ~2^-22)
__device__ __forceinline__ float sigm(float x) {
    return rcp_ap(1.0f + ex2_ap(-1.4426950408889634f * x));
}
// tanh(x) = 1 - 2/(2^(2x*log2 e) + 1)
__device__ __forceinline__ float tanh_e(float x) {
    float e = ex2_ap(2.8853900817779268f * x);
    return 1.0f - 2.0f * rcp_ap(e + 1.0f);
}

// ---- kernel 1: xdot[t,b,g] = <inputs[t,b,:], W[g,0:256]> + bias[g] ---------
// One warp per (t,b) pair; 8 warps per block.
__global__ void k_xdot(const float* __restrict__ in, const float* __restrict__ W,
                       const float* __restrict__ bias) {
    __shared__ float4 sW[4][64];   // W[g][0:256] as float4
    int tid = threadIdx.x;
    for (int i = tid; i < 4 * 64; i += 256) {
        int g = i >> 6, c = i & 63;
        // W row stride = 512 floats = 128 float4; first 64 float4 = x-part
        sW[g][c] = reinterpret_cast<const float4*>(W)[g * 128 + c];
    }
    __syncthreads();

    int warp = tid >> 5, lane = tid & 31;
    long p = (long)blockIdx.x * 8 + warp;        // (t*B + b) pair index
    const float4* src = reinterpret_cast<const float4*>(in) + p * 64;
    float4 a0 = src[lane];
    float4 a1 = src[lane + 32];

    float s[4];
#pragma unroll
    for (int g = 0; g < 4; g++) {
        float4 w = sW[g][lane];
        float t = a0.x * w.x + a0.y * w.y + a0.z * w.z + a0.w * w.w;
        w = sW[g][lane + 32];
        t += a1.x * w.x + a1.y * w.y + a1.z * w.z + a1.w * w.w;
        s[g] = t;
    }
#pragma unroll
    for (int g = 0; g < 4; g++) {
#pragma unroll
        for (int o = 16; o; o >>= 1) s[g] += __shfl_xor_sync(0xffffffffu, s[g], o);
    }
    if (lane == 0) {
        float4 r = make_float4(s[0] + bias[0], s[1] + bias[1],
                               s[2] + bias[2], s[3] + bias[3]);
        reinterpret_cast<float4*>(g_xdot)[p] = r;
    }
}

// ---- kernel 2: scalar recurrence, one thread per batch element -------------
__global__ void k_rec(const float* __restrict__ W) {
    __shared__ float swh[4];
    int tid = threadIdx.x;
    int g = tid >> 5, lane = tid & 31;
    {   // whsum[g] = sum_h W[g, D+h]
        const float* wr = W + g * 512 + 256;
        float s = 0.f;
#pragma unroll
        for (int k = 0; k < 8; k++) s += wr[lane + k * 32];
#pragma unroll
        for (int o = 16; o; o >>= 1) s += __shfl_xor_sync(0xffffffffu, s, o);
        if (lane == 0) swh[g] = s;
    }
    __syncthreads();
    float w0 = swh[0], w1 = swh[1], w2 = swh[2], w3 = swh[3];

    int b = tid;
    float h = 0.f, c = 0.f;
    const float4* xd4 = reinterpret_cast<const float4*>(g_xdot);
    float4 xd = xd4[b];
    for (int t = 0; t < T_DIM; t++) {
        float4 nxt = xd4[(t + 1) * B_DIM + b];   // prefetch (off-chain)
        float f  = sigm(sin_ap(fmaf(h, w0, xd.x)));
        float i  = sigm(sin_ap(fmaf(h, w1, xd.y)));
        float gg = tanh_e(sin_ap(fmaf(h, w2, xd.z)));
        float o  = sigm(sin_ap(fmaf(h, w3, xd.w)));
        c = fmaf(f, c, i * gg);
        h = o * tanh_e(c);
        g_h[t * B_DIM + b] = h;
        xd = nxt;
    }
    g_c[b] = c;
}

// ---- kernel 3: broadcast h over H into the output, plus hx/cx tails --------
__global__ void k_bcast(float* __restrict__ out) {
    long idx = (long)blockIdx.x * 256 + threadIdx.x;   // float4 index
    const long S4  = (long)T_DIM * B_DIM * H_DIM / 4;  // 8388608
    const long BH4 = (long)B_DIM * H_DIM / 4;          // 8192
    if (idx >= S4 + 2 * BH4) return;
    float v;
    if (idx < S4) {
        v = g_h[idx >> 6];                                      // stacked
    } else if (idx < S4 + BH4) {
        v = g_h[(long)(T_DIM - 1) * B_DIM + ((idx - S4) >> 6)]; // hx (== last row)
    } else {
        v = g_c[(idx - S4 - BH4) >> 6];                         // cx
    }
    reinterpret_cast<float4*>(out)[idx] = make_float4(v, v, v, v);
}

extern "C" void kernel_launch(void* const* d_in, const int* in_sizes, int n_in,
                              void* d_out, int out_size) {
    const float* in   = (const float*)d_in[0];   // [T,B,D]
    const float* W    = (const float*)d_in[1];   // [4, D+H]
    const float* bias = (const float*)d_in[2];   // [4]
    // d_in[3] (qw) mathematically has no effect on the output.
    float* out = (float*)d_out;

    k_xdot<<<(T_DIM * B_DIM) / 8, 256>>>(in, W, bias);
    k_rec<<<1, 128>>>(W);
    long total4 = (long)T_DIM * B_DIM * H_DIM / 4 + 2 * (long)B_DIM * H_DIM / 4;
    k_bcast<<<(int)((total4 + 255) / 256), 256>>>(out);
}

// round 2
// speedup vs baseline: 1.1804x; 1.1804x over previous
#include <cuda_runtime.h>

#define T_DIM 1024
#define B_DIM 128
#define D_DIM 256
#define H_DIM 256

// Scratch (allocation-free rule: __device__ globals).
// g_xdot padded by 8*B_DIM float4 so the 5-deep recurrence prefetch stays in bounds.
__device__ __align__(16) float g_xdot[(T_DIM * B_DIM + 8 * B_DIM) * 4];
__device__ __align__(16) float g_h[T_DIM * B_DIM];
__device__ __align__(16) float g_c[B_DIM];

// ---- fast math helpers -----------------------------------------------------
__device__ __forceinline__ float sin_ap(float x) {
    float r; asm("sin.approx.f32 %0, %1;" : "=f"(r) : "f"(x)); return r;
}
__device__ __forceinline__ float ex2_ap(float x) {
    float r; asm("ex2.approx.f32 %0, %1;" : "=f"(r) : "f"(x)); return r;
}
__device__ __forceinline__ float rcp_ap(float x) {
    float r; asm("rcp.approx.f32 %0, %1;" : "=f"(r) : "f"(x)); return r;
}
// MUFU sigmoid: 2 fma-pipe ops + 2 MUFU ops (used where MUFU budget allows)
__device__ __forceinline__ float sigm_mufu(float x) {
    return rcp_ap(1.0f + ex2_ap(-1.4426950408889634f * x));
}
// Polynomial sigmoid, valid |s|<=1 (input is sin(.)), abs err ~2e-7.
// sigmoid(s) = 0.5 + s*(A0 + A1 u + ... + A5 u^5), u = s^2 (tanh(s/2)/2 Taylor)
__device__ __forceinline__ float sigm_poly(float s) {
    const float A0 = 0.25f, A1 = -2.0833333e-2f, A2 = 2.0833333e-3f,
                A3 = -2.1081349e-4f, A4 = 2.1356790e-5f, A5 = -2.1638685e-6f;
    float u  = s * s;
    float b0 = fmaf(A1, u, A0);
    float b1 = fmaf(A3, u, A2);
    float b2 = fmaf(A5, u, A4);
    float u2 = u * u;
    float u4 = u2 * u2;
    float p  = fmaf(b2, u4, fmaf(b1, u2, b0));
    return fmaf(s, p, 0.5f);
}
// tanh, continued-fraction depth 5, valid |x|<=1 (err ~1e-8). One rcp.
__device__ __forceinline__ float tanh_p5(float x) {
    float u = x * x;
    float n = fmaf(u + 105.0f, u, 945.0f);
    float d = fmaf(fmaf(15.0f, u, 420.0f), u, 945.0f);
    return x * n * rcp_ap(d);
}
// tanh, continued-fraction depth 6, valid |x|<=2.2 (err ~3e-6). One rcp.
__device__ __forceinline__ float tanh_p6(float x) {
    float u  = x * x;
    float u2 = u * u;
    float n  = fmaf(fmaf(21.0f, u, 1260.0f), u, 10395.0f);
    float d  = fmaf(u2, u + 210.0f, fmaf(4725.0f, u, 10395.0f));
    return x * n * rcp_ap(d);
}

// ---- kernel 1: xdot[t,b,g] = <inputs[t,b,:], W[g,0:256]> + bias[g] ---------
// One warp per (t,b) pair; 8 warps per block. 6-shuffle packed reduction.
__global__ void k_xdot(const float* __restrict__ in, const float* __restrict__ W,
                       const float* __restrict__ bias) {
    __shared__ float4 sW[4][64];   // W[g][0:256] as float4
    int tid = threadIdx.x;
    for (int i = tid; i < 4 * 64; i += 256) {
        int g = i >> 6, c = i & 63;
        sW[g][c] = reinterpret_cast<const float4*>(W)[g * 128 + c];  // row stride 128 f4
    }
    __syncthreads();

    int warp = tid >> 5, lane = tid & 31;
    long p = (long)blockIdx.x * 8 + warp;        // (t*B + b) pair index
    const float4* src = reinterpret_cast<const float4*>(in) + p * 64;
    float4 a0 = src[lane];
    float4 a1 = src[lane + 32];

    float s[4];
#pragma unroll
    for (int g = 0; g < 4; g++) {
        float4 w = sW[g][lane];
        float t = a0.x * w.x + a0.y * w.y + a0.z * w.z + a0.w * w.w;
        w = sW[g][lane + 32];
        t += a1.x * w.x + a1.y * w.y + a1.z * w.z + a1.w * w.w;
        s[g] = t;
    }
    const unsigned FULL = 0xffffffffu;
    // level 1 (xor 1): pack (s0,s1) and (s2,s3)
    bool b0 = lane & 1;
    float t01 = b0 ? s[0] : s[1];
    float k01 = b0 ? s[1] : s[0];
    k01 += __shfl_xor_sync(FULL, t01, 1);
    float t23 = b0 ? s[2] : s[3];
    float k23 = b0 ? s[3] : s[2];
    k23 += __shfl_xor_sync(FULL, t23, 1);
    // level 2 (xor 2): pack (k01,k23) -> lane%4 == g holds s[g] over its 4-lane group
    bool b1 = lane & 2;
    float tv = b1 ? k01 : k23;
    float kv = b1 ? k23 : k01;
    kv += __shfl_xor_sync(FULL, tv, 2);
    // levels 3-5: plain butterflies
    kv += __shfl_xor_sync(FULL, kv, 4);
    kv += __shfl_xor_sync(FULL, kv, 8);
    kv += __shfl_xor_sync(FULL, kv, 16);
    if (lane < 4)
        g_xdot[p * 4 + lane] = kv + bias[lane];
}

// ---- kernel 2: scalar recurrence, one thread per batch element -------------
__global__ void k_rec(const float* __restrict__ W) {
    __shared__ float swh[4];
    int tid = threadIdx.x;
    int g = tid >> 5, lane = tid & 31;
    {   // whsum[g] = sum_h W[g, D+h]
        const float* wr = W + g * 512 + 256;
        float s = 0.f;
#pragma unroll
        for (int k = 0; k < 8; k++) s += wr[lane + k * 32];
#pragma unroll
        for (int o = 16; o; o >>= 1) s += __shfl_xor_sync(0xffffffffu, s, o);
        if (lane == 0) swh[g] = s;
    }
    __syncthreads();
    float w0 = swh[0], w1 = swh[1], w2 = swh[2], w3 = swh[3];

    int b = tid;
    const float4* xd4 = reinterpret_cast<const float4*>(g_xdot);

    // init: h=0 -> lin^0 = xdot^0
    float4 x0 = xd4[b];
    float lf = x0.x, li = x0.y, lg = x0.z, lo = x0.w;
    float4 buf[4];               // holds xd_{t+1}..xd_{t+4}
#pragma unroll
    for (int k = 0; k < 4; k++) buf[k] = xd4[(k + 1) * B_DIM + b];

    float c = 0.f;
    float* gh = g_h + b;
#pragma unroll 4
    for (int t = 0; t < T_DIM; t++) {
        float4 nxt = buf[t & 3];
        buf[t & 3] = xd4[(t + 5) * B_DIM + b];     // 5-deep prefetch (off-chain)

        float sf = sin_ap(lf);
        float si = sin_ap(li);
        float sg = sin_ap(lg);
        float so = sin_ap(lo);
        float f  = sigm_mufu(sf);     // MUFU pipe
        float i  = sigm_poly(si);     // FMA pipe (shortest: feeds i*g early)
        float gg = tanh_p5(sg);       // critical gate path
        float o  = sigm_mufu(so);     // MUFU pipe; ready before tc
        c = fmaf(f, c, i * gg);
        float tc = tanh_p6(c);
        // fold h = o*tc into next lin: lin = (w*o)*tc + xd  (saves chain depth)
        lf = fmaf(w0 * o, tc, nxt.x);
        li = fmaf(w1 * o, tc, nxt.y);
        lg = fmaf(w2 * o, tc, nxt.z);
        lo = fmaf(w3 * o, tc, nxt.w);
        gh[t * B_DIM] = o * tc;       // off-chain
    }
    g_c[b] = c;
}

// ---- kernel 3: broadcast h over H into the output, plus hx/cx tails --------
__global__ void k_bcast(float* __restrict__ out) {
    long idx = (long)blockIdx.x * 256 + threadIdx.x;   // float4 index
    const long S4  = (long)T_DIM * B_DIM * H_DIM / 4;  // 8388608
    const long BH4 = (long)B_DIM * H_DIM / 4;          // 8192
    if (idx >= S4 + 2 * BH4) return;
    float v;
    if (idx < S4) {
        v = g_h[idx >> 6];                                      // stacked
    } else if (idx < S4 + BH4) {
        v = g_h[(long)(T_DIM - 1) * B_DIM + ((idx - S4) >> 6)]; // hx (== last row)
    } else {
        v = g_c[(idx - S4 - BH4) >> 6];                         // cx
    }
    reinterpret_cast<float4*>(out)[idx] = make_float4(v, v, v, v);
}

extern "C" void kernel_launch(void* const* d_in, const int* in_sizes, int n_in,
                              void* d_out, int out_size) {
    const float* in   = (const float*)d_in[0];   // [T,B,D]
    const float* W    = (const float*)d_in[1];   // [4, D+H]
    const float* bias = (const float*)d_in[2];   // [4]
    // d_in[3] (qw) mathematically has no effect on the output.
    float* out = (float*)d_out;

    k_xdot<<<(T_DIM * B_DIM) / 8, 256>>>(in, W, bias);
    k_rec<<<1, 128>>>(W);
    long total4 = (long)T_DIM * B_DIM * H_DIM / 4 + 2 * (long)B_DIM * H_DIM / 4;
    k_bcast<<<(int)((total4 + 255) / 256), 256>>>(out);
}

// round 3
// speedup vs baseline: 1.3969x; 1.1835x over previous
#include <cuda_runtime.h>

#define T_DIM 1024
#define B_DIM 128
#define H_DIM 256
#define CHUNK 64
#define NCHUNK 16                 // 16 * 64 = 1024 steps
#define NCTA 148
#define NWORK (NCTA - 1)          // 147 worker CTAs
#define NWARPW (NWORK * 8)        // 1176 worker warps
#define NTHW (NWORK * 256)        // 37632 worker threads

// Scratch (__device__ globals; allocation-free rule).
__device__ __align__(16) float g_xdot[(T_DIM + 8) * B_DIM * 4]; // [t][b][4], padded
__device__ __align__(16) float g_h[B_DIM * T_DIM];              // [b][t]
__device__ __align__(16) float g_c[B_DIM];
__device__ int g_xdone[NCHUNK];
__device__ int g_rdone;

// ---- fast math helpers -----------------------------------------------------
__device__ __forceinline__ float sin_ap(float x) {
    float r; asm("sin.approx.f32 %0, %1;" : "=f"(r) : "f"(x)); return r;
}
__device__ __forceinline__ float rcp_ap(float x) {
    float r; asm("rcp.approx.f32 %0, %1;" : "=f"(r) : "f"(x)); return r;
}
// Polynomial sigmoid, valid |s|<=1 (input is sin(.)), abs err ~2e-7. FMA pipe only.
__device__ __forceinline__ float sigm_poly(float s) {
    const float A0 = 0.25f, A1 = -2.0833333e-2f, A2 = 2.0833333e-3f,
                A3 = -2.1081349e-4f, A4 = 2.1356790e-5f, A5 = -2.1638685e-6f;
    float u  = s * s;
    float b0 = fmaf(A1, u, A0);
    float b1 = fmaf(A3, u, A2);
    float b2 = fmaf(A5, u, A4);
    float u2 = u * u;
    float u4 = u2 * u2;
    float p  = fmaf(b2, u4, fmaf(b1, u2, b0));
    return fmaf(s, p, 0.5f);
}
// tanh continued fraction depth 5, valid |x|<=1 (err ~1e-8). One rcp.
__device__ __forceinline__ float tanh_p5(float x) {
    float u = x * x;
    float n = fmaf(u + 105.0f, u, 945.0f);
    float d = fmaf(fmaf(15.0f, u, 420.0f), u, 945.0f);
    return x * n * rcp_ap(d);
}
// tanh continued fraction depth 6, valid |x|<=2.2 (err ~3e-6; |c|<=2.07 provably). One rcp.
__device__ __forceinline__ float tanh_p6(float x) {
    float u  = x * x;
    float u2 = u * u;
    float n  = fmaf(fmaf(21.0f, u, 1260.0f), u, 10395.0f);
    float d  = fmaf(u2, u + 210.0f, fmaf(4725.0f, u, 10395.0f));
    return x * n * rcp_ap(d);
}

__device__ __forceinline__ void waitGe(const int* p, int v) {
    while (*(volatile const int*)p < v) __nanosleep(64);
}

// ---- zero the cross-CTA flags (runs before the fused kernel each call) -----
__global__ void k_zero() {
    int i = threadIdx.x;
    if (i < NCHUNK) g_xdone[i] = 0;
    if (i == NCHUNK) g_rdone = 0;
}

// ---- fused persistent kernel ----------------------------------------------
__global__ __launch_bounds__(256, 1) void k_fused(const float* __restrict__ in,
                                                  const float* __restrict__ Wt,
                                                  const float* __restrict__ bias,
                                                  float* __restrict__ out) {
    const int cta = blockIdx.x;
    const int tid = threadIdx.x;
    const int lane = tid & 31;

    if (cta == 0) {
        // ================= recurrence CTA =================
        if (tid >= 128) return;            // 4 warps, one per SMSP
        // whsum[g] computed redundantly per warp (no cross-warp sync needed)
        float wh[4];
#pragma unroll
        for (int g = 0; g < 4; g++) {
            const float* wr = Wt + g * 512 + 256;
            float s = 0.f;
#pragma unroll
            for (int k = 0; k < 8; k++) s += wr[lane + k * 32];
#pragma unroll
            for (int o = 16; o; o >>= 1) s += __shfl_xor_sync(0xffffffffu, s, o);
            wh[g] = s;
        }
        float w0 = wh[0], w1 = wh[1], w2 = wh[2], w3 = wh[3];

        const int b = tid;
        const float4* xd4 = reinterpret_cast<const float4*>(g_xdot);
        float4* gh4 = reinterpret_cast<float4*>(g_h);

        // wait for xdot chunk 0, then init lin_0 and prefetch ring (t=1..4)
        if (tid == 0) waitGe(&g_xdone[0], NWORK);
        asm volatile("bar.sync 1, 128;" ::: "memory");
        float4 x0 = xd4[b];
        float lf = x0.x, li = x0.y, lg = x0.z, lo = x0.w;
        float4 buf[4];
#pragma unroll
        for (int k = 0; k < 4; k++) buf[k] = xd4[(k + 1) * B_DIM + b];

        float c = 0.f;
        float4 hv;
        for (int ch = 0; ch < NCHUNK; ch++) {
            // gate on chunk ch AND ch+1 (prefetch reads up to t+5 into next chunk)
            int c2 = (ch + 1 < NCHUNK) ? ch + 1 : NCHUNK - 1;
            if (tid == 0) { waitGe(&g_xdone[ch], NWORK); waitGe(&g_xdone[c2], NWORK); }
            asm volatile("bar.sync 1, 128;" ::: "memory");

            const int t0 = ch * CHUNK;
#pragma unroll 4
            for (int t = t0; t < t0 + CHUNK; t++) {
                float4 nxt = buf[t & 3];
                buf[t & 3] = xd4[(t + 5) * B_DIM + b];   // 5-deep prefetch (off-chain)

                float sf = sin_ap(lf);
                float si = sin_ap(li);
                float sg = sin_ap(lg);
                float so = sin_ap(lo);
                float f  = sigm_poly(sf);    // FMA pipe
                float i_ = sigm_poly(si);    // FMA pipe
                float gg = tanh_p5(sg);      // critical gate path
                float o  = sigm_poly(so);    // FMA pipe
                c = fmaf(f, c, i_ * gg);
                float wo0 = w0 * o, wo1 = w1 * o, wo2 = w2 * o, wo3 = w3 * o;
                float tc = tanh_p6(c);
                lf = fmaf(wo0, tc, nxt.x);
                li = fmaf(wo1, tc, nxt.y);
                lg = fmaf(wo2, tc, nxt.z);
                lo = fmaf(wo3, tc, nxt.w);
                float h = o * tc;
                int ph = t & 3;
                if (ph == 0) hv.x = h;
                else if (ph == 1) hv.y = h;
                else if (ph == 2) hv.z = h;
                else { hv.w = h; gh4[(b * T_DIM + t - 3) >> 2] = hv; }
            }
            if (ch == NCHUNK - 1) g_c[b] = c;
            __threadfence();
            asm volatile("bar.sync 1, 128;" ::: "memory");
            if (tid == 0) *(volatile int*)&g_rdone = (ch + 1) * CHUNK;
        }
        return;
    }

    // ================= worker CTAs: xdot then bcast =================
    __shared__ float4 sW[4][64];
    for (int i = tid; i < 4 * 64; i += 256) {
        int g = i >> 6, cc = i & 63;
        sW[g][cc] = reinterpret_cast<const float4*>(Wt)[g * 128 + cc];
    }
    __syncthreads();

    const int warp = tid >> 5;
    const int wg = (cta - 1) * 8 + warp;          // 0..1175
    const float bv = (lane < 4) ? bias[lane] : 0.f;
    const float4* in4 = reinterpret_cast<const float4*>(in);
    const unsigned FULL = 0xffffffffu;

    for (int ch = 0; ch < NCHUNK; ch++) {
        const int pe = (ch + 1) * CHUNK * B_DIM;
        for (int p = ch * CHUNK * B_DIM + wg; p < pe; p += NWARPW) {
            const float4* src = in4 + (long)p * 64;
            float4 a0 = src[lane];
            float4 a1 = src[lane + 32];
            float s[4];
#pragma unroll
            for (int g = 0; g < 4; g++) {
                float4 w = sW[g][lane];
                float t = a0.x * w.x + a0.y * w.y + a0.z * w.z + a0.w * w.w;
                w = sW[g][lane + 32];
                t += a1.x * w.x + a1.y * w.y + a1.z * w.z + a1.w * w.w;
                s[g] = t;
            }
            // packed 6-shuffle reduction of 4 sums
            bool b0 = lane & 1;
            float t01 = b0 ? s[0] : s[1];
            float k01 = b0 ? s[1] : s[0];
            k01 += __shfl_xor_sync(FULL, t01, 1);
            float t23 = b0 ? s[2] : s[3];
            float k23 = b0 ? s[3] : s[2];
            k23 += __shfl_xor_sync(FULL, t23, 1);
            bool b1 = lane & 2;
            float tv = b1 ? k01 : k23;
            float kv = b1 ? k23 : k01;
            kv += __shfl_xor_sync(FULL, tv, 2);
            kv += __shfl_xor_sync(FULL, kv, 4);
            kv += __shfl_xor_sync(FULL, kv, 8);
            kv += __shfl_xor_sync(FULL, kv, 16);
            if (lane < 4) g_xdot[p * 4 + lane] = kv + bv;
        }
        __threadfence();
        __syncthreads();
        if (tid == 0) atomicAdd(&g_xdone[ch], 1);
    }

    // ---- bcast phase: trail the recurrence ----
    float4* out4 = reinterpret_cast<float4*>(out);
    const int widx = (cta - 1) * 256 + tid;
    const long S4 = (long)T_DIM * B_DIM * H_DIM / 4;   // 8388608
    for (int ch = 0; ch < NCHUNK; ch++) {
        if (tid == 0) waitGe(&g_rdone, (ch + 1) * CHUNK);
        __syncthreads();
        const long base = (long)ch * CHUNK * (B_DIM * H_DIM / 4);
        const long end  = base + (long)CHUNK * (B_DIM * H_DIM / 4);
        for (long i = base + widx; i < end; i += NTHW) {
            int t = (int)(i >> 13);            // 8192 float4 per t
            int b = (int)(i >> 6) & 127;
            float v = g_h[b * T_DIM + t];
            out4[i] = make_float4(v, v, v, v);
        }
    }
    // tails: hx (== h at t=1023) and cx  (rec fully done after chunk-15 wait)
    for (long i = S4 + widx; i < S4 + 16384; i += NTHW) {
        int r = (int)(i - S4);
        float v;
        if (r < 8192) v = g_h[(r >> 6) * T_DIM + (T_DIM - 1)];
        else          v = g_c[(r - 8192) >> 6];
        out4[i] = make_float4(v, v, v, v);
    }
}

extern "C" void kernel_launch(void* const* d_in, const int* in_sizes, int n_in,
                              void* d_out, int out_size) {
    const float* in   = (const float*)d_in[0];   // [T,B,D]
    const float* Wt   = (const float*)d_in[1];   // [4, D+H]
    const float* bias = (const float*)d_in[2];   // [4]
    // d_in[3] (qw) mathematically has no effect on the output.
    float* out = (float*)d_out;

    k_zero<<<1, 32>>>();
    k_fused<<<NCTA, 256>>>(in, Wt, bias, out);
}